// round 17
// baseline (speedup 1.0000x reference)
#include <cuda_runtime.h>
#include <cuda_bf16.h>
#include <cuda_fp16.h>
#include <cstdint>

#define NN 50000
#define EE 800000
#define DD 128
#define NEV 4
#define EPSV 1e-8f
#define NBLK ((NN + 255) / 256)      // 196
#define GEMM_BLKS (((NN + 127) / 128) * NEV)   // 391*4 = 1564
#define SCAT_BLKS ((EE + 255) / 256)           // 3125

// ---------------- scratch (device globals; no allocation allowed) ----------------
__device__ __half d_hh[(size_t)NN * NEV * DD];   // [n][e][f] fp16, 51.2 MB
__device__ __nv_bfloat16 d_xh[(size_t)NN * DD];  // x split hi
__device__ __nv_bfloat16 d_xl[(size_t)NN * DD];  // x split lo
__device__ float d_ssrc[NN * NEV];
__device__ float d_sdst[NN * NEV];
__device__ unsigned d_max1u[NEV];
__device__ unsigned d_max2u[NEV];
__device__ int d_cnt[NN];                        // zeroed at end of each invocation (scatter path)
__device__ int d_off[NN + 1];
__device__ int d_cur[NN];
__device__ int d_csr[EE];
__device__ int d_bsum[NBLK];
__device__ __nv_bfloat16 d_Wth[NEV * DD * DD];   // W^T hi: [e][f][k]
__device__ __nv_bfloat16 d_Wtl[NEV * DD * DD];   // W^T lo

__device__ __forceinline__ unsigned fenc(float f) {
    unsigned u = __float_as_uint(f);
    return (u & 0x80000000u) ? ~u : (u | 0x80000000u);
}
__device__ __forceinline__ float fdec(unsigned u) {
    u = (u & 0x80000000u) ? (u & 0x7fffffffu) : ~u;
    return __uint_as_float(u);
}
__device__ __forceinline__ float lrelu(float v) { return v > 0.f ? v : 0.01f * v; }

__device__ __forceinline__ uint32_t pack_bf2(float lo, float hi) {
    __nv_bfloat162 p;
    p.x = __float2bfloat16(lo);
    p.y = __float2bfloat16(hi);
    return *(uint32_t*)&p;
}

__device__ __forceinline__ void unpack8(uint4 u, float* f) {
    float2 a = __half22float2(*(__half2*)&u.x);
    float2 b = __half22float2(*(__half2*)&u.y);
    float2 c = __half22float2(*(__half2*)&u.z);
    float2 d = __half22float2(*(__half2*)&u.w);
    f[0] = a.x; f[1] = a.y; f[2] = b.x; f[3] = b.y;
    f[4] = c.x; f[5] = c.y; f[6] = d.x; f[7] = d.y;
}

__device__ __forceinline__ void mma_bf16(float& c0, float& c1, float& c2, float& c3,
                                         uint32_t a0, uint32_t a1, uint32_t a2, uint32_t a3,
                                         uint32_t b0, uint32_t b1) {
    asm volatile(
        "mma.sync.aligned.m16n8k16.row.col.f32.bf16.bf16.f32 "
        "{%0,%1,%2,%3}, {%4,%5,%6,%7}, {%8,%9}, {%0,%1,%2,%3};\n"
        : "+f"(c0), "+f"(c1), "+f"(c2), "+f"(c3)
        : "r"(a0), "r"(a1), "r"(a2), "r"(a3), "r"(b0), "r"(b1));
}

__device__ __forceinline__ void ldsm_x4(uint32_t* r, uint32_t addr) {
    asm volatile("ldmatrix.sync.aligned.m8n8.x4.shared.b16 {%0,%1,%2,%3}, [%4];"
                 : "=r"(r[0]), "=r"(r[1]), "=r"(r[2]), "=r"(r[3]) : "r"(addr));
}

// smem layout (word offsets), K staged in halves of 64.
#define ROWW 36
#define AH_W 0
#define AL_W (128 * ROWW)
#define BH_W (2 * 128 * ROWW)
#define BL_W (3 * 128 * ROWW)
#define SRED_W (4 * 128 * ROWW)
#define SMEM_WORDS (SRED_W + 256)
#define SMEM_BYTES (SMEM_WORDS * 4)
#define MT_STRIDE_B (16 * ROWW * 4)
#define LO_OFF_B (128 * ROWW * 4)

// ---------------- fused prep: x split || W split || histogram ----------------
__global__ void prep_kernel(const float* __restrict__ x,
                            const float* __restrict__ W,
                            const int* __restrict__ adj) {
    int i = blockIdx.x * blockDim.x + threadIdx.x;   // grid covers NN*32 = 1.6M
    if (i < NN * 32) {
        float4 v = ((const float4*)x)[i];
        float h0 = __bfloat162float(__float2bfloat16(v.x));
        float h1 = __bfloat162float(__float2bfloat16(v.y));
        float h2 = __bfloat162float(__float2bfloat16(v.z));
        float h3 = __bfloat162float(__float2bfloat16(v.w));
        uint2 hv, lv;
        hv.x = pack_bf2(v.x, v.y); hv.y = pack_bf2(v.z, v.w);
        lv.x = pack_bf2(v.x - h0, v.y - h1); lv.y = pack_bf2(v.z - h2, v.w - h3);
        ((uint2*)d_xh)[i] = hv;
        ((uint2*)d_xl)[i] = lv;
    }
    if (i < NEV * DD * DD) {
        int e = i >> 14;
        int k = (i >> 7) & 127;
        int f = i & 127;
        float v = W[i];
        __nv_bfloat16 hb = __float2bfloat16(v);
        __nv_bfloat16 lb = __float2bfloat16(v - __bfloat162float(hb));
        int o = ((e * DD + f) << 7) + k;
        d_Wth[o] = hb;
        d_Wtl[o] = lb;
    }
    if (i < EE) atomicAdd(&d_cnt[adj[i]], 1);
}

// ---------------- multi-block scan: stage 1 (also zeroes max accumulators) ----------------
__global__ void blockscan_kernel() {
    __shared__ int wsum[8];
    int blk = blockIdx.x, t = threadIdx.x, lane = t & 31, w = t >> 5;
    // maxu consumed by previous invocation's agg; written by the LATER gemm_scatter.
    // Zeroing here is ordered correctly within this invocation.
    if (blk == 0 && t < NEV) { d_max1u[t] = 0u; d_max2u[t] = 0u; }
    int i = blk * 256 + t;
    int v = (i < NN) ? d_cnt[i] : 0;
    int s = v;
#pragma unroll
    for (int o = 1; o < 32; o <<= 1) {
        int y = __shfl_up_sync(0xffffffffu, s, o);
        if (lane >= o) s += y;
    }
    if (lane == 31) wsum[w] = s;
    __syncthreads();
    if (t == 0) {
        int acc = 0;
#pragma unroll
        for (int j = 0; j < 8; j++) { int x = wsum[j]; wsum[j] = acc; acc += x; }
        d_bsum[blk] = acc;
    }
    __syncthreads();
    if (i < NN) d_off[i] = wsum[w] + s - v;
}

// ---------------- scan stage 2: per-block prefix + add ----------------
__global__ void addoff_kernel() {
    __shared__ int wsum[8];
    __shared__ int s_boff;
    int t = threadIdx.x, lane = t & 31, w = t >> 5;
    int blk = blockIdx.x;
    int v = (t < blk) ? d_bsum[t] : 0;    // NBLK=196 <= 256
#pragma unroll
    for (int o = 16; o > 0; o >>= 1) v += __shfl_xor_sync(0xffffffffu, v, o);
    if (lane == 0) wsum[w] = v;
    __syncthreads();
    if (t == 0) {
        int acc = 0;
#pragma unroll
        for (int j = 0; j < 8; j++) acc += wsum[j];
        s_boff = acc;
    }
    __syncthreads();
    int i = blk * 256 + t;
    if (i < NN) {
        int o = d_off[i] + s_boff;
        d_off[i] = o;
        d_cur[i] = o;
    }
    if (i == 0) d_off[NN] = EE;
}

// ---------------- fused GEMM (bf16x3 mma + ldmatrix, fused s + max) ∪ scatter ----------------
__global__ void __launch_bounds__(256, 2) gemm_scatter_kernel(const float* __restrict__ a,
                                                              const int* __restrict__ adj) {
    int bid = blockIdx.x;
    int t = threadIdx.x;

    if (bid >= GEMM_BLKS) {
        // ---------- scatter path (+ restore d_cnt = 0 for the next invocation) ----------
        int i = (bid - GEMM_BLKS) * 256 + t;
        if (i < NN) d_cnt[i] = 0;   // consumed by blockscan earlier this invocation
        if (i < EE) {
            int s = adj[i];
            int d = adj[EE + i];
            int p = atomicAdd(&d_cur[s], 1);
            d_csr[p] = d;
        }
        return;
    }

    // ---------- gemm path ----------
    extern __shared__ uint32_t sm[];
    uint32_t smb = (uint32_t)__cvta_generic_to_shared(sm);
    int lane = t & 31, wid = t >> 5;
    int e = bid & 3;
    int n0 = (bid >> 2) * 128;

    float* s1r = (float*)(sm + SRED_W);
    float* s2r = s1r + 128;
    if (t < 128) { s1r[t] = 0.f; s2r[t] = 0.f; }

    int warpM = (wid >> 1) * 32;
    int warpN = (wid & 1) * 64;
    int g = lane >> 2, th = lane & 3;
    int lrow = lane & 15, lhalf = lane >> 4;

    uint32_t aab = smb + (uint32_t)(AH_W + (warpM + lrow) * ROWW + lhalf * 4) * 4;
    uint32_t bab = smb + (uint32_t)(BH_W + (warpN + lrow) * ROWW + lhalf * 4) * 4;

    float acc[2][8][4];
#pragma unroll
    for (int mt = 0; mt < 2; mt++)
#pragma unroll
        for (int nt = 0; nt < 8; nt++)
#pragma unroll
            for (int j = 0; j < 4; j++) acc[mt][nt][j] = 0.f;

    const uint2* xh2 = (const uint2*)d_xh;
    const uint2* xl2 = (const uint2*)d_xl;
    const uint2* wh2 = (const uint2*)(d_Wth + e * DD * DD);
    const uint2* wl2 = (const uint2*)(d_Wtl + e * DD * DD);

#pragma unroll
    for (int s = 0; s < 2; s++) {
        if (s) __syncthreads();

#pragma unroll
        for (int i = 0; i < 8; i++) {
            int q = i * 256 + t;
            int row = q >> 4;
            int kq = q & 15;
            int n = n0 + row;
            uint2 hv = make_uint2(0u, 0u), lv = make_uint2(0u, 0u);
            if (n < NN) {
                hv = xh2[n * 32 + s * 16 + kq];
                lv = xl2[n * 32 + s * 16 + kq];
            }
            *(uint2*)(sm + AH_W + row * ROWW + 2 * kq) = hv;
            *(uint2*)(sm + AL_W + row * ROWW + 2 * kq) = lv;
        }
#pragma unroll
        for (int i = 0; i < 8; i++) {
            int q = i * 256 + t;
            int row = q >> 4;
            int kq = q & 15;
            *(uint2*)(sm + BH_W + row * ROWW + 2 * kq) = wh2[row * 32 + s * 16 + kq];
            *(uint2*)(sm + BL_W + row * ROWW + 2 * kq) = wl2[row * 32 + s * 16 + kq];
        }
        __syncthreads();

#pragma unroll
        for (int kk = 0; kk < 4; kk++) {
            uint32_t kb = kk * 32;
            uint32_t ah[2][4], al[2][4], bh[4][4], bl[4][4];
            ldsm_x4(ah[0], aab + kb);
            ldsm_x4(ah[1], aab + MT_STRIDE_B + kb);
            ldsm_x4(al[0], aab + LO_OFF_B + kb);
            ldsm_x4(al[1], aab + LO_OFF_B + MT_STRIDE_B + kb);
#pragma unroll
            for (int q = 0; q < 4; q++) {
                ldsm_x4(bh[q], bab + q * MT_STRIDE_B + kb);
                ldsm_x4(bl[q], bab + LO_OFF_B + q * MT_STRIDE_B + kb);
            }
#pragma unroll
            for (int nt = 0; nt < 8; nt++) {
                int p = nt >> 1, sl = nt & 1;
                uint32_t b0h = bh[p][sl], b1h = bh[p][2 + sl];
                uint32_t b0l = bl[p][sl], b1l = bl[p][2 + sl];
#pragma unroll
                for (int mt = 0; mt < 2; mt++) {
                    mma_bf16(acc[mt][nt][0], acc[mt][nt][1], acc[mt][nt][2], acc[mt][nt][3],
                             ah[mt][0], ah[mt][1], ah[mt][2], ah[mt][3], b0h, b1h);
                    mma_bf16(acc[mt][nt][0], acc[mt][nt][1], acc[mt][nt][2], acc[mt][nt][3],
                             ah[mt][0], ah[mt][1], ah[mt][2], ah[mt][3], b0l, b1l);
                    mma_bf16(acc[mt][nt][0], acc[mt][nt][1], acc[mt][nt][2], acc[mt][nt][3],
                             al[mt][0], al[mt][1], al[mt][2], al[mt][3], b0h, b1h);
                }
            }
        }
    }

    const float* a1 = a + e * 2 * DD;
    const float* a2 = a1 + DD;
#pragma unroll
    for (int mt = 0; mt < 2; mt++) {
#pragma unroll
        for (int half = 0; half < 2; half++) {
            int row_local = warpM + mt * 16 + half * 8 + g;
            int n = n0 + row_local;
            float p1 = 0.f, p2 = 0.f;
#pragma unroll
            for (int nt = 0; nt < 8; nt++) {
                int col = warpN + nt * 8 + 2 * th;
                float c0 = acc[mt][nt][half * 2];
                float c1 = acc[mt][nt][half * 2 + 1];
                p1 += c0 * __ldg(a1 + col) + c1 * __ldg(a1 + col + 1);
                p2 += c0 * __ldg(a2 + col) + c1 * __ldg(a2 + col + 1);
                if (n < NN)
                    *(__half2*)&d_hh[((size_t)n * NEV + e) * DD + col] = __floats2half2_rn(c0, c1);
            }
            p1 += __shfl_xor_sync(0xffffffffu, p1, 1);
            p1 += __shfl_xor_sync(0xffffffffu, p1, 2);
            p2 += __shfl_xor_sync(0xffffffffu, p2, 1);
            p2 += __shfl_xor_sync(0xffffffffu, p2, 2);
            if (th == 0) {
                atomicAdd(&s1r[row_local], p1);   // exactly 2 adds/addr -> deterministic
                atomicAdd(&s2r[row_local], p2);
            }
        }
    }
    __syncthreads();
    if (t < 128) {
        int n = n0 + t;
        float v1 = s1r[t], v2 = s2r[t];
        bool ok = (n < NN);
        if (ok) {
            d_ssrc[n * NEV + e] = v1;
            d_sdst[n * NEV + e] = v2;
        } else {
            v1 = -1e30f; v2 = -1e30f;
        }
#pragma unroll
        for (int o = 16; o > 0; o >>= 1) {
            v1 = fmaxf(v1, __shfl_xor_sync(0xffffffffu, v1, o));
            v2 = fmaxf(v2, __shfl_xor_sync(0xffffffffu, v2, o));
        }
        if (lane == 0) {
            atomicMax(&d_max1u[e], fenc(v1));
            atomicMax(&d_max2u[e], fenc(v2));
        }
    }
}

// ---------------- aggregate v2: one warp per node, __ldcg uint4 loads ----------------
__global__ void agg_kernel(const float* __restrict__ x,
                           const float* __restrict__ envw,
                           float* __restrict__ out) {
    int wid  = (blockIdx.x * blockDim.x + threadIdx.x) >> 5;
    int lane = threadIdx.x & 31;
    if (wid >= NN) return;
    int n = wid;
    int hi = lane >> 4;
    int er0 = hi, er1 = 2 + hi;

    float m[NEV], ss[NEV];
#pragma unroll
    for (int e = 0; e < NEV; e++) {
        // softmax bound: m >= true max logit; exact value cancels in num/denom
        m[e]  = lrelu(fdec(d_max1u[e]) + fdec(d_max2u[e]));
        ss[e] = d_ssrc[n * NEV + e];
    }
    float4 sdn = *(const float4*)&d_sdst[n * NEV];
    float sdv[NEV] = {sdn.x, sdn.y, sdn.z, sdn.w};

    float w0 = __expf(lrelu(ss[er0] + sdv[er0]) - m[er0]);
    float w1 = __expf(lrelu(ss[er1] + sdv[er1]) - m[er1]);
    float den0 = w0, den1 = w1;

    float acc0[8], acc1[8];
    {
        const char* hp = (const char*)d_hh + (size_t)n * 1024 + lane * 16;
        uint4 u0 = __ldcg((const uint4*)hp);
        uint4 u1 = __ldcg((const uint4*)(hp + 512));
        float f0[8], f1[8];
        unpack8(u0, f0); unpack8(u1, f1);
#pragma unroll
        for (int k = 0; k < 8; k++) { acc0[k] = w0 * f0[k]; acc1[k] = w1 * f1[k]; }
    }

    int start = d_off[n], end = d_off[n + 1];
    int e_l = lane & 3, j_l = lane >> 2;
    float ss_l = ss[e_l], m_l = m[e_l];

    for (int base = start; base < end; base += 8) {
        int idx = base + j_l;
        int dl = 0;
        float wl = 0.f;
        if (idx < end) {
            dl = __ldcs(&d_csr[idx]);
            float sv = d_sdst[dl * NEV + e_l];
            wl = __expf(lrelu(ss_l + sv) - m_l);
        }
        int cnt = end - base; if (cnt > 8) cnt = 8;
#pragma unroll
        for (int j = 0; j < 8; j++) {
            if (j >= cnt) break;
            int d = __shfl_sync(0xffffffffu, dl, j * 4);
            float we0 = __shfl_sync(0xffffffffu, wl, j * 4 + er0);
            float we1 = __shfl_sync(0xffffffffu, wl, j * 4 + er1);
            const char* hp = (const char*)d_hh + (size_t)d * 1024 + lane * 16;
            uint4 u0 = __ldcg((const uint4*)hp);
            uint4 u1 = __ldcg((const uint4*)(hp + 512));
            float f0[8], f1[8];
            unpack8(u0, f0); unpack8(u1, f1);
            den0 += we0; den1 += we1;
#pragma unroll
            for (int k = 0; k < 8; k++) {
                acc0[k] += we0 * f0[k];
                acc1[k] += we1 * f1[k];
            }
        }
    }

    float4 ew = *(const float4*)&envw[n * NEV];
    float c0 = ((hi == 0) ? ew.x : ew.y) / (den0 + EPSV);
    float c1 = ((hi == 0) ? ew.z : ew.w) / (den1 + EPSV);
    float tot[8];
#pragma unroll
    for (int k = 0; k < 8; k++) tot[k] = c0 * acc0[k] + c1 * acc1[k];
#pragma unroll
    for (int k = 0; k < 8; k++) tot[k] += __shfl_xor_sync(0xffffffffu, tot[k], 16);

    int fi = (lane & 15) * 8 + hi * 4;
    float4 xv = *(const float4*)&x[(size_t)n * DD + fi];
    float4 o;
    o.x = xv.x + tot[hi * 4 + 0];
    o.y = xv.y + tot[hi * 4 + 1];
    o.z = xv.z + tot[hi * 4 + 2];
    o.w = xv.w + tot[hi * 4 + 3];
    *(float4*)&out[(size_t)n * DD + fi] = o;
}

// ---------------- launcher ----------------
extern "C" void kernel_launch(void* const* d_in, const int* in_sizes, int n_in,
                              void* d_out, int out_size) {
    const float* x    = (const float*)d_in[0];
    const int*   adj  = (const int*)d_in[1];
    const float* envw = (const float*)d_in[2];
    const float* W    = (const float*)d_in[3];
    const float* a    = (const float*)d_in[4];
    float* out = (float*)d_out;

    cudaFuncSetAttribute(gemm_scatter_kernel, cudaFuncAttributeMaxDynamicSharedMemorySize, SMEM_BYTES);

    prep_kernel<<<(NN * 32 + 255) / 256, 256>>>(x, W, adj);
    blockscan_kernel<<<NBLK, 256>>>();
    addoff_kernel<<<NBLK, 256>>>();
    gemm_scatter_kernel<<<GEMM_BLKS + SCAT_BLKS, 256, SMEM_BYTES>>>(a, adj);
    agg_kernel<<<(NN + 7) / 8, 256>>>(x, envw, out);
}